// round 16
// baseline (speedup 1.0000x reference)
#include <cuda_runtime.h>
#include <math.h>
#include <stdint.h>

#define NPTS  8192
#define DIM   128
#define CAP   2048
#define SCOLS 512

// ---------------- device scratch (no allocations allowed) ----------------
__device__ float         g_dsamp[(size_t)NPTS * SCOLS];  // 16 MB sample dists
__device__ uint2         g_cand[(size_t)NPTS * CAP];     // 134 MB candidates
__device__ int           g_cnt[NPTS];
__device__ float         g_B[NPTS];
__device__ int           g_hist[128];
__device__ float         g_sq[NPTS];
__device__ unsigned char g_lab[NPTS];
__device__ float         g_loss[NPTS];
__device__ float         g_accv[NPTS];
__device__ float         g_tpv[NPTS];
__device__ float         g_tnv[NPTS];
__device__ int           g_is32;

// ---------------- packed fp32x2 helpers ----------------
__device__ __forceinline__ void fma2(unsigned long long& d,
                                     unsigned long long a,
                                     unsigned long long b) {
    asm("fma.rn.f32x2 %0, %1, %2, %0;" : "+l"(d) : "l"(a), "l"(b));
}
__device__ __forceinline__ unsigned long long pack2(float lo, float hi) {
    unsigned long long r;
    asm("mov.b64 %0, {%1, %2};" : "=l"(r) : "r"(__float_as_uint(lo)), "r"(__float_as_uint(hi)));
    return r;
}
__device__ __forceinline__ void unpack2(unsigned long long v, float& lo, float& hi) {
    unsigned a, b;
    asm("mov.b64 {%0, %1}, %2;" : "=r"(a), "=r"(b) : "l"(v));
    lo = __uint_as_float(a);
    hi = __uint_as_float(b);
}

// ---------------- shared tile GEMM: 128x128 distances ----------------
// Identical fp sequence wherever called -> bit-identical distances.
__device__ __forceinline__ void tile_dists(const float* __restrict__ X,
                                           int rowbase, int colbase, int tid,
                                           float acc[8][8]) {
    __shared__ float As[16][128];
    __shared__ float Bs[16][128];
    const int tx = tid & 15;
    const int ty = tid >> 4;

    unsigned long long acc2[8][4];
#pragma unroll
    for (int a = 0; a < 8; a++)
#pragma unroll
        for (int c = 0; c < 4; c++) acc2[a][c] = 0ull;

    for (int k0 = 0; k0 < DIM; k0 += 16) {
#pragma unroll
        for (int r = 0; r < 2; r++) {
            int pos = tid + r * 256;
            int row = pos >> 2;
            int kc  = pos & 3;
            float4 va = *(const float4*)&X[(size_t)(rowbase + row) * DIM + k0 + kc * 4];
            As[kc * 4 + 0][row] = va.x;
            As[kc * 4 + 1][row] = va.y;
            As[kc * 4 + 2][row] = va.z;
            As[kc * 4 + 3][row] = va.w;
            float4 vb = *(const float4*)&X[(size_t)(colbase + row) * DIM + k0 + kc * 4];
            Bs[kc * 4 + 0][row] = vb.x;
            Bs[kc * 4 + 1][row] = vb.y;
            Bs[kc * 4 + 2][row] = vb.z;
            Bs[kc * 4 + 3][row] = vb.w;
        }
        __syncthreads();
#pragma unroll
        for (int kk = 0; kk < 16; kk++) {
            float ar[8], br[8];
            *(float4*)&ar[0] = *(const float4*)&As[kk][ty * 8];
            *(float4*)&ar[4] = *(const float4*)&As[kk][ty * 8 + 4];
            *(float4*)&br[0] = *(const float4*)&Bs[kk][tx * 8];
            *(float4*)&br[4] = *(const float4*)&Bs[kk][tx * 8 + 4];
            unsigned long long b2[4];
#pragma unroll
            for (int c = 0; c < 4; c++) b2[c] = pack2(br[2 * c], br[2 * c + 1]);
#pragma unroll
            for (int a = 0; a < 8; a++) {
                unsigned long long a2 = pack2(ar[a], ar[a]);
#pragma unroll
                for (int c = 0; c < 4; c++) fma2(acc2[a][c], a2, b2[c]);
            }
        }
        __syncthreads();
    }

    float sqa[8], sqb[8];
#pragma unroll
    for (int a = 0; a < 8; a++) sqa[a] = g_sq[rowbase + ty * 8 + a];
#pragma unroll
    for (int c = 0; c < 8; c++) sqb[c] = g_sq[colbase + tx * 8 + c];

#pragma unroll
    for (int a = 0; a < 8; a++)
#pragma unroll
        for (int c = 0; c < 4; c++) {
            float lo, hi;
            unpack2(acc2[a][c], lo, hi);
            acc[a][2 * c]     = sqrtf(fmaxf(sqa[a] + sqb[2 * c]     - 2.0f * lo, 1e-12f));
            acc[a][2 * c + 1] = sqrtf(fmaxf(sqa[a] + sqb[2 * c + 1] - 2.0f * hi, 1e-12f));
        }
}

// ---------------- small setup kernels ----------------
__global__ void detect_kernel(const int* __restrict__ t) {
    int local = 0;
    for (int j = threadIdx.x; j < 4096; j += blockDim.x) local |= t[2 * j + 1];
#pragma unroll
    for (int off = 16; off; off >>= 1) local |= __shfl_down_sync(0xffffffffu, local, off);
    __shared__ int s[8];
    if ((threadIdx.x & 31) == 0) s[threadIdx.x >> 5] = local;
    __syncthreads();
    if (threadIdx.x == 0) {
        int f = 0;
        for (int w = 0; w < 8; w++) f |= s[w];
        g_is32 = (f != 0);
    }
}

__global__ void zero_kernel() {
    int t = blockIdx.x * blockDim.x + threadIdx.x;
    if (t < NPTS) g_cnt[t] = 0;
    if (t < 128) g_hist[t] = 0;
}

__global__ void conv_kernel(const void* __restrict__ t) {
    int is32 = g_is32;
    int i = blockIdx.x * blockDim.x + threadIdx.x;
    if (i < NPTS) {
        int v = is32 ? ((const int*)t)[i] : (int)(((const long long*)t)[i]);
        g_lab[i] = (unsigned char)(v & 127);
        atomicAdd(&g_hist[v & 127], 1);
    }
}

__global__ void sq_kernel(const float* __restrict__ X) {
    int i = blockIdx.x;
    int tid = threadIdx.x;  // 128 threads
    float v = X[i * DIM + tid];
    v *= v;
#pragma unroll
    for (int off = 16; off; off >>= 1) v += __shfl_down_sync(0xffffffffu, v, off);
    __shared__ float s[4];
    if ((tid & 31) == 0) s[tid >> 5] = v;
    __syncthreads();
    if (tid == 0) g_sq[i] = s[0] + s[1] + s[2] + s[3];
}

// ---------------- sample distances: all rows x cols [0,512) ----------------
__global__ void __launch_bounds__(256, 2) sample_kernel(const float* __restrict__ X) {
    const int bx = blockIdx.x & 3;         // col block 0..3
    const int by = blockIdx.x >> 2;        // row block 0..63
    const int rowbase = by * 128;
    const int colbase = bx * 128;
    const int tid = threadIdx.x;
    const int tx = tid & 15;
    const int ty = tid >> 4;

    float acc[8][8];
    tile_dists(X, rowbase, colbase, tid, acc);

#pragma unroll
    for (int a = 0; a < 8; a++) {
        int row = rowbase + ty * 8 + a;
        float4 o0 = make_float4(acc[a][0], acc[a][1], acc[a][2], acc[a][3]);
        float4 o1 = make_float4(acc[a][4], acc[a][5], acc[a][6], acc[a][7]);
        *(float4*)&g_dsamp[(size_t)row * SCOLS + colbase + tx * 8]     = o0;
        *(float4*)&g_dsamp[(size_t)row * SCOLS + colbase + tx * 8 + 4] = o1;
    }
}

// ---------------- per-row bound: exact 17th of 512 sample dists ----------
__global__ void __launch_bounds__(512) bound_kernel() {
    const int i = blockIdx.x;
    const int tid = threadIdx.x;
    const int lane = tid & 31;
    const int wid = tid >> 5;  // 0..15
    const float INF = __int_as_float(0x7f800000);

    __shared__ float s_pmin[272];
    __shared__ float s_b;

    float v = g_dsamp[(size_t)i * SCOLS + tid];
    if (tid == i) v = INF;  // self-distance only when i < 512

    int r = 0;
#pragma unroll
    for (int o = 1; o < 32; o++) {
        float ov = __shfl_xor_sync(0xffffffffu, v, o);
        int ol = lane ^ o;
        r += (ov < v) || (ov == v && ol < lane);
    }
    if (r < 17) s_pmin[wid * 17 + r] = v;
    __syncthreads();

    if (tid < 272) {
        float val = s_pmin[tid];
        int rr = 0;
        for (int s = 0; s < 272; s++) {
            float ov = s_pmin[s];
            rr += (ov < val) || (ov == val && s < tid);
        }
        if (rr == 16) s_b = val;  // exact 17th smallest value of the 512
    }
    __syncthreads();
    if (tid == 0) g_B[i] = s_b * 1.000002f;  // ulp-safety inflation
}

// ---------------- main pass: symmetric tiles, append candidates ----------
__global__ void __launch_bounds__(256, 2) dist_main_kernel(const float* __restrict__ X) {
    const int t = blockIdx.x;
    int b = (int)((sqrtf(8.0f * (float)t + 1.0f) - 1.0f) * 0.5f);
    while ((b * (b + 1)) / 2 > t) b--;
    while (((b + 1) * (b + 2)) / 2 <= t) b++;
    const int by = t - (b * (b + 1)) / 2;
    const int bx = b;
    const int rowbase = by * 128;
    const int colbase = bx * 128;
    const int tid = threadIdx.x;
    const int tx = tid & 15;
    const int ty = tid >> 4;

    float acc[8][8];
    tile_dists(X, rowbase, colbase, tid, acc);

    float Brow[8], Bcol[8];
#pragma unroll
    for (int a = 0; a < 8; a++) Brow[a] = g_B[rowbase + ty * 8 + a];
#pragma unroll
    for (int c = 0; c < 8; c++) Bcol[c] = g_B[colbase + tx * 8 + c];

    const bool diag = (bx == by);
#pragma unroll
    for (int a = 0; a < 8; a++) {
        int r = rowbase + ty * 8 + a;
#pragma unroll
        for (int cc = 0; cc < 8; cc++) {
            int col = colbase + tx * 8 + cc;
            float d = acc[a][cc];
            if (r == col) continue;
            if (d <= Brow[a]) {
                int p = atomicAdd(&g_cnt[r], 1);
                if (p < CAP)
                    g_cand[(size_t)r * CAP + p] = make_uint2(__float_as_uint(d), (unsigned)col);
            }
            // symmetric side; skip on diagonal tiles (pair already covered)
            if (!diag && d <= Bcol[cc]) {
                int p = atomicAdd(&g_cnt[col], 1);
                if (p < CAP)
                    g_cand[(size_t)col * CAP + p] = make_uint2(__float_as_uint(d), (unsigned)r);
            }
        }
    }
}

// ---------------- row finalize: exact 17th + sums from candidates ---------
__global__ void __launch_bounds__(256) row_finalize(const float* __restrict__ X) {
    const int i = blockIdx.x;
    const int tid = threadIdx.x;
    const int lane = tid & 31;
    const int wid = tid >> 5;
    const float INF = __int_as_float(0x7f800000);

    __shared__ float sv[CAP];
    __shared__ int   sj[CAP];
    __shared__ float sxi[128];
    __shared__ float s_pmin[136];
    __shared__ float s_pivot;
    __shared__ float s_thr;
    __shared__ int   s_ccnt, s_bcnt;
    __shared__ float sb_v[32];
    __shared__ int   sb_j[32];
    __shared__ int   s_fpw[8];
    __shared__ float s_red[4];
    __shared__ int   s_fpg;
    __shared__ float s_ps, s_ns;
    __shared__ int   s_cp, s_cn, s_need;

    const int total = g_cnt[i];
    const int myl = g_lab[i];
    const float sqi = g_sq[i];
    if (tid == 0) { s_ccnt = 0; s_bcnt = 0; s_thr = INF; s_need = 0; }

    int cnt;
    if (total <= CAP) {
        // -------- normal path: load candidate list --------
        cnt = total;
        for (int t = tid; t < cnt; t += 256) {
            uint2 e = g_cand[(size_t)i * CAP + t];
            sv[t] = __uint_as_float(e.x);
            sj[t] = (int)e.y;
        }
        __syncthreads();
    } else {
        // -------- fallback: recompute the whole row from X (rare) --------
        for (int t = tid; t < 128; t += 256) sxi[t] = X[(size_t)i * DIM + t];
        __syncthreads();
        float v[32];
        for (int c = 0; c < 32; c++) {
            int j = c * 256 + tid;
            const float* xr = X + (size_t)j * DIM;
            float dot = 0.0f;
            for (int k = 0; k < 128; k++) dot = fmaf(sxi[k], xr[k], dot);
            v[c] = (j == i) ? INF : sqrtf(fmaxf(sqi + g_sq[j] - 2.0f * dot, 1e-12f));
        }
        float mn = v[0];
        for (int c = 1; c < 32; c++) mn = fminf(mn, v[c]);
        {
            int r = 0;
#pragma unroll
            for (int o = 1; o < 32; o++) {
                float ov = __shfl_xor_sync(0xffffffffu, mn, o);
                int ol = lane ^ o;
                r += (ov < mn) || (ov == mn && ol < lane);
            }
            if (r < 17) s_pmin[wid * 17 + r] = mn;
        }
        __syncthreads();
        if (tid < 136) {
            float val = s_pmin[tid];
            int r = 0;
            for (int s = 0; s < 136; s++) {
                float ov = s_pmin[s];
                r += (ov < val) || (ov == val && s < tid);
            }
            if (r == 16) s_pivot = val;
        }
        __syncthreads();
        const float pivot = s_pivot;
        for (int c = 0; c < 32; c++) {
            float val = v[c];
            bool sel = (val <= pivot);
            unsigned m = __ballot_sync(0xffffffffu, sel);
            if (sel) {
                int leader = __ffs(m) - 1;
                int base = 0;
                if (lane == leader) base = atomicAdd(&s_ccnt, __popc(m));
                base = __shfl_sync(m, base, leader);
                int pos = base + __popc(m & ((1u << lane) - 1));
                if (pos < CAP) {
                    sv[pos] = val;
                    sj[pos] = c * 256 + tid;
                }
            }
        }
        __syncthreads();
        cnt = min(s_ccnt, CAP);
    }

    // -------- exact 17th smallest by (value, index) rank --------
    for (int t = tid; t < cnt; t += 256) {
        float mv = sv[t];
        int mj = sj[t];
        int r = 0;
        for (int s = 0; s < cnt; s++) {
            float ov = sv[s];
            r += (ov < mv) || (ov == mv && sj[s] < mj);
        }
        if (r == 16) s_thr = mv;
    }
    __syncthreads();
    const float thr = s_thr;

    // -------- gather below-threshold entries (<= 16 of them) --------
    for (int t = tid; t < cnt; t += 256) {
        if (sv[t] < thr) {
            int p = atomicAdd(&s_bcnt, 1);
            if (p < 32) { sb_v[p] = sv[t]; sb_j[p] = sj[t]; }
        }
    }

    // -------- first positive (label-only, distance-independent) --------
    {
        int fp = NPTS;
        for (int c = 0; c < 32 && fp == NPTS; c++) {
            int j = c * 256 + tid;
            if (j != i && g_lab[j] == myl) fp = j;
        }
#pragma unroll
        for (int off = 16; off; off >>= 1)
            fp = min(fp, __shfl_down_sync(0xffffffffu, fp, off));
        if (lane == 0) s_fpw[wid] = fp;
    }
    __syncthreads();

    // -------- deterministic sums (single thread, ascending j) --------
    if (tid == 0) {
        int fp = NPTS;
        for (int w = 0; w < 8; w++) fp = min(fp, s_fpw[w]);
        s_fpg = fp;

        int n = min(s_bcnt, 32);
        // insertion sort by j
        for (int a = 1; a < n; a++) {
            float tv = sb_v[a]; int tj = sb_j[a];
            int p = a - 1;
            while (p >= 0 && sb_j[p] > tj) {
                sb_v[p + 1] = sb_v[p]; sb_j[p + 1] = sb_j[p]; p--;
            }
            sb_v[p + 1] = tv; sb_j[p + 1] = tj;
        }
        float ps = 0.0f, ns = 0.0f;
        int cp = 0, cn = 0;
        for (int a = 0; a < n; a++) {
            float e = expf(-sb_v[a]);
            if (g_lab[sb_j[a]] == myl) { ps += e; cp++; }
            else                        { ns += e; cn++; }
        }
        s_ps = ps; s_ns = ns; s_cp = cp; s_cn = cn;
        s_need = (cp == 0 && fp < NPTS) ? 1 : 0;
    }
    __syncthreads();

    // -------- fallback pos: dist(i, first_pos) via parallel dot --------
    if (s_need) {
        const int fp = s_fpg;
        float part = 0.0f;
        if (tid < 128) part = X[(size_t)i * DIM + tid] * X[(size_t)fp * DIM + tid];
#pragma unroll
        for (int off = 16; off; off >>= 1)
            part += __shfl_down_sync(0xffffffffu, part, off);
        if (tid < 128 && lane == 0) s_red[wid] = part;
    }
    __syncthreads();

    if (tid == 0) {
        const int fp = s_fpg;
        bool haspos = (fp < NPTS);
        bool anyneg = (g_hist[myl] < NPTS);
        bool validr = haspos && anyneg;
        float pos_eff;
        if (s_cp == 0) {
            if (s_need) {
                float dot = s_red[0] + s_red[1] + s_red[2] + s_red[3];
                float dfb = sqrtf(fmaxf(sqi + g_sq[fp] - 2.0f * dot, 1e-12f));
                pos_eff = expf(-dfb);
            } else pos_eff = 1.0f;
        } else pos_eff = s_ps;
        float loss_i = validr ? logf((pos_eff + s_ns) / pos_eff) : 0.0f;
        int cpa = (s_cp == 0) ? 1 : s_cp;
        g_loss[i] = loss_i;
        g_accv[i] = (validr && cpa > s_cn) ? 1.0f : 0.0f;
        g_tpv[i]  = validr ? (float)s_cp : 0.0f;
        g_tnv[i]  = validr ? (float)s_cn : 0.0f;
    }
}

// ---------------- deterministic final reduction ----------------
__global__ void finalize_kernel(float* __restrict__ out) {
    __shared__ float s0[256], s1[256], s2[256], s3[256];
    int tid = threadIdx.x;
    float a = 0, b = 0, c = 0, d = 0;
    for (int j = tid; j < NPTS; j += 256) {
        a += g_loss[j]; b += g_accv[j]; c += g_tpv[j]; d += g_tnv[j];
    }
    s0[tid] = a; s1[tid] = b; s2[tid] = c; s3[tid] = d;
    __syncthreads();
    for (int off = 128; off; off >>= 1) {
        if (tid < off) {
            s0[tid] += s0[tid + off];
            s1[tid] += s1[tid + off];
            s2[tid] += s2[tid + off];
            s3[tid] += s3[tid + off];
        }
        __syncthreads();
    }
    if (tid == 0) {
        const float inv = 1.0f / (float)NPTS;
        out[0] = s0[0] * inv;  // loss
        out[1] = s1[0] * inv;  // accuracy
        out[2] = s2[0] * inv;  // tp
        out[3] = s3[0] * inv;  // tn
    }
}

extern "C" void kernel_launch(void* const* d_in, const int* in_sizes, int n_in,
                              void* d_out, int out_size) {
    const float* X = (const float*)d_in[0];
    const void* T = d_in[1];
    float* out = (float*)d_out;
    (void)in_sizes; (void)n_in; (void)out_size;

    detect_kernel<<<1, 256>>>((const int*)T);
    zero_kernel<<<32, 256>>>();
    conv_kernel<<<32, 256>>>(T);
    sq_kernel<<<NPTS, 128>>>(X);
    sample_kernel<<<256, 256>>>(X);          // 64 row-blocks x 4 col-blocks
    bound_kernel<<<NPTS, 512>>>();
    const int ntiles = (NPTS / 128) * (NPTS / 128 + 1) / 2;  // 2080
    dist_main_kernel<<<ntiles, 256>>>(X);
    row_finalize<<<NPTS, 256>>>(X);
    finalize_kernel<<<1, 256>>>(out);
}

// round 17
// speedup vs baseline: 2.4544x; 2.4544x over previous
#include <cuda_runtime.h>
#include <math.h>

#define NPTS 8192
#define DIM  128
#define CAND_MAX 1024

// ---------------- device scratch (no allocations allowed) ----------------
__device__ float         g_dist[(size_t)NPTS * NPTS];  // 256 MB distance matrix
__device__ float         g_sq[NPTS];
__device__ unsigned char g_lab[NPTS];
__device__ float         g_loss[NPTS];
__device__ float         g_accv[NPTS];
__device__ float         g_tpv[NPTS];
__device__ float         g_tnv[NPTS];
__device__ int           g_is32;

// ---------------- packed fp32x2 helpers (Blackwell FFMA2 path) -----------
__device__ __forceinline__ void fma2(unsigned long long& d,
                                     unsigned long long a,
                                     unsigned long long b) {
    asm("fma.rn.f32x2 %0, %1, %2, %0;" : "+l"(d) : "l"(a), "l"(b));
}
__device__ __forceinline__ unsigned long long pack2(float lo, float hi) {
    unsigned long long r;
    asm("mov.b64 %0, {%1, %2};" : "=l"(r) : "r"(__float_as_uint(lo)), "r"(__float_as_uint(hi)));
    return r;
}
__device__ __forceinline__ void unpack2(unsigned long long v, float& lo, float& hi) {
    unsigned a, b;
    asm("mov.b64 {%0, %1}, %2;" : "=r"(a), "=r"(b) : "l"(v));
    lo = __uint_as_float(a);
    hi = __uint_as_float(b);
}

// ---------------- dtype detection for targets (int32 vs int64) -----------
__global__ void detect_kernel(const int* __restrict__ t) {
    int local = 0;
    for (int j = threadIdx.x; j < 4096; j += blockDim.x) local |= t[2 * j + 1];
#pragma unroll
    for (int off = 16; off; off >>= 1) local |= __shfl_down_sync(0xffffffffu, local, off);
    __shared__ int s[8];
    if ((threadIdx.x & 31) == 0) s[threadIdx.x >> 5] = local;
    __syncthreads();
    if (threadIdx.x == 0) {
        int f = 0;
        for (int w = 0; w < 8; w++) f |= s[w];
        g_is32 = (f != 0);
    }
}

__global__ void conv_kernel(const void* __restrict__ t) {
    int is32 = g_is32;
    int i = blockIdx.x * blockDim.x + threadIdx.x;
    if (i < NPTS) {
        int v = is32 ? ((const int*)t)[i] : (int)(((const long long*)t)[i]);
        g_lab[i] = (unsigned char)v;
    }
}

// ---------------- squared norms ----------------
__global__ void sq_kernel(const float* __restrict__ X) {
    int i = blockIdx.x;
    int tid = threadIdx.x;  // 128 threads
    float v = X[i * DIM + tid];
    v *= v;
#pragma unroll
    for (int off = 16; off; off >>= 1) v += __shfl_down_sync(0xffffffffu, v, off);
    __shared__ float s[4];
    if ((tid & 31) == 0) s[tid >> 5] = v;
    __syncthreads();
    if (tid == 0) g_sq[i] = s[0] + s[1] + s[2] + s[3];
}

// ---------------- chunk loader for the double-buffered GEMM --------------
__device__ __forceinline__ void load_chunk(const float* __restrict__ X,
                                           int rowbase, int colbase, int tid,
                                           int k0,
                                           float (*As)[128], float (*Bs)[128]) {
#pragma unroll
    for (int r = 0; r < 2; r++) {
        int pos = tid + r * 256;
        int row = pos >> 2;
        int kc  = pos & 3;
        float4 va = *(const float4*)&X[(size_t)(rowbase + row) * DIM + k0 + kc * 4];
        As[kc * 4 + 0][row] = va.x;
        As[kc * 4 + 1][row] = va.y;
        As[kc * 4 + 2][row] = va.z;
        As[kc * 4 + 3][row] = va.w;
        float4 vb = *(const float4*)&X[(size_t)(colbase + row) * DIM + k0 + kc * 4];
        Bs[kc * 4 + 0][row] = vb.x;
        Bs[kc * 4 + 1][row] = vb.y;
        Bs[kc * 4 + 2][row] = vb.z;
        Bs[kc * 4 + 3][row] = vb.w;
    }
}

// ---------------- distance matrix: symmetric tiled fp32x2 "GEMM" ----------
// Double-buffered smem: next chunk's LDG/STS issue before this chunk's math,
// one barrier per chunk (8 total vs 16).
__global__ void __launch_bounds__(256, 2) dist_kernel(const float* __restrict__ X) {
    __shared__ float As[2][16][128];
    __shared__ float Bs[2][16][128];

    const int t = blockIdx.x;
    int b = (int)((sqrtf(8.0f * (float)t + 1.0f) - 1.0f) * 0.5f);
    while ((b * (b + 1)) / 2 > t) b--;
    while (((b + 1) * (b + 2)) / 2 <= t) b++;
    const int by = t - (b * (b + 1)) / 2;   // row tile
    const int bx = b;                       // col tile (>= by)

    const int tid = threadIdx.x;
    const int tx = tid & 15;
    const int ty = tid >> 4;
    const int rowbase = by * 128;
    const int colbase = bx * 128;

    unsigned long long acc2[8][4];
#pragma unroll
    for (int a = 0; a < 8; a++)
#pragma unroll
        for (int c = 0; c < 4; c++) acc2[a][c] = 0ull;

    load_chunk(X, rowbase, colbase, tid, 0, As[0], Bs[0]);
    __syncthreads();

    for (int ch = 0; ch < 8; ch++) {
        const int cur = ch & 1;
        if (ch < 7)
            load_chunk(X, rowbase, colbase, tid, (ch + 1) * 16, As[cur ^ 1], Bs[cur ^ 1]);
#pragma unroll
        for (int kk = 0; kk < 16; kk++) {
            float ar[8], br[8];
            *(float4*)&ar[0] = *(const float4*)&As[cur][kk][ty * 8];
            *(float4*)&ar[4] = *(const float4*)&As[cur][kk][ty * 8 + 4];
            *(float4*)&br[0] = *(const float4*)&Bs[cur][kk][tx * 8];
            *(float4*)&br[4] = *(const float4*)&Bs[cur][kk][tx * 8 + 4];
            unsigned long long b2[4];
#pragma unroll
            for (int c = 0; c < 4; c++) b2[c] = pack2(br[2 * c], br[2 * c + 1]);
#pragma unroll
            for (int a = 0; a < 8; a++) {
                unsigned long long a2 = pack2(ar[a], ar[a]);
#pragma unroll
                for (int c = 0; c < 4; c++) fma2(acc2[a][c], a2, b2[c]);
            }
        }
        __syncthreads();
    }

    float sqa[8], sqb[8];
#pragma unroll
    for (int a = 0; a < 8; a++) sqa[a] = g_sq[rowbase + ty * 8 + a];
#pragma unroll
    for (int c = 0; c < 8; c++) sqb[c] = g_sq[colbase + tx * 8 + c];

    float acc[8][8];
#pragma unroll
    for (int a = 0; a < 8; a++)
#pragma unroll
        for (int c = 0; c < 4; c++) {
            float lo, hi;
            unpack2(acc2[a][c], lo, hi);
            acc[a][2 * c]     = sqrtf(fmaxf(sqa[a] + sqb[2 * c]     - 2.0f * lo, 1e-12f));
            acc[a][2 * c + 1] = sqrtf(fmaxf(sqa[a] + sqb[2 * c + 1] - 2.0f * hi, 1e-12f));
        }

#pragma unroll
    for (int a = 0; a < 8; a++) {
        int row = rowbase + ty * 8 + a;
        float4 o0 = make_float4(acc[a][0], acc[a][1], acc[a][2], acc[a][3]);
        float4 o1 = make_float4(acc[a][4], acc[a][5], acc[a][6], acc[a][7]);
        *(float4*)&g_dist[(size_t)row * NPTS + colbase + tx * 8]     = o0;
        *(float4*)&g_dist[(size_t)row * NPTS + colbase + tx * 8 + 4] = o1;
    }

    if (bx != by) {
#pragma unroll
        for (int c = 0; c < 8; c++) {
            int col = colbase + tx * 8 + c;
            float4 p0 = make_float4(acc[0][c], acc[1][c], acc[2][c], acc[3][c]);
            float4 p1 = make_float4(acc[4][c], acc[5][c], acc[6][c], acc[7][c]);
            *(float4*)&g_dist[(size_t)col * NPTS + rowbase + ty * 8]     = p0;
            *(float4*)&g_dist[(size_t)col * NPTS + rowbase + ty * 8 + 4] = p1;
        }
    }
}

// ---------------- per-row kernel: tight parallel pivot + gather + select ---
// (R13 structure; __expf/__logf for the transcendental path)
__global__ void __launch_bounds__(256) row_kernel() {
    const int i = blockIdx.x;
    const int tid = threadIdx.x;
    const int lane = tid & 31;
    const int wid = tid >> 5;
    const float INF = __int_as_float(0x7f800000);

    __shared__ int   swarr[8];
    __shared__ float s_pmin[136];
    __shared__ float cand_v[CAND_MAX];
    __shared__ int   cand_j[CAND_MAX];
    __shared__ int   s_cnt;
    __shared__ float s_pivot;
    __shared__ float s_thr;
    __shared__ float sps[8], sns[8], sfpd[8];
    __shared__ int   scp[8], scn[8], sfp[8], san[8];

    if (tid == 0) s_cnt = 0;

    float v[32];
    const float4* drow4 = (const float4*)(g_dist + (size_t)i * NPTS);
#pragma unroll
    for (int c = 0; c < 8; c++) {
        float4 t4 = drow4[c * 256 + tid];
        v[c * 4 + 0] = t4.x;
        v[c * 4 + 1] = t4.y;
        v[c * 4 + 2] = t4.z;
        v[c * 4 + 3] = t4.w;
    }
    if (tid == ((i & 1023) >> 2))
        v[((i >> 10) << 2) + (i & 3)] = INF;

    float mn = v[0];
#pragma unroll
    for (int c = 1; c < 32; c++) mn = fminf(mn, v[c]);

    {
        int r = 0;
#pragma unroll
        for (int o = 1; o < 32; o++) {
            float ov = __shfl_xor_sync(0xffffffffu, mn, o);
            int ol = lane ^ o;
            r += (ov < mn) || (ov == mn && ol < lane);
        }
        if (r < 17) s_pmin[wid * 17 + r] = mn;
    }
    __syncthreads();

    if (tid < 136) {
        float val = s_pmin[tid];
        int r = 0;
        for (int s = 0; s < 136; s++) {
            float ov = s_pmin[s];
            r += (ov < val) || (ov == val && s < tid);
        }
        if (r == 16) s_pivot = val;
    }
    __syncthreads();
    const float pivot = s_pivot;

#pragma unroll
    for (int c = 0; c < 8; c++) {
#pragma unroll
        for (int k = 0; k < 4; k++) {
            float val = v[c * 4 + k];
            bool sel = (val <= pivot);
            unsigned m = __ballot_sync(0xffffffffu, sel);
            if (sel) {
                int leader = __ffs(m) - 1;
                int base = 0;
                if (lane == leader) base = atomicAdd(&s_cnt, __popc(m));
                base = __shfl_sync(m, base, leader);
                int pos = base + __popc(m & ((1u << lane) - 1));
                if (pos < CAND_MAX) {
                    cand_v[pos] = val;
                    cand_j[pos] = c * 1024 + 4 * tid + k;
                }
            }
        }
    }
    __syncthreads();
    const int cnt = s_cnt;

    if (cnt <= CAND_MAX) {
        for (int t = tid; t < cnt; t += 256) {
            float mv = cand_v[t];
            int mj = cand_j[t];
            int r = 0;
            for (int s = 0; s < cnt; s++) {
                float ov = cand_v[s];
                r += (ov < mv) || (ov == mv && cand_j[s] < mj);
            }
            if (r == 16) s_thr = mv;
        }
    } else {
        unsigned cur = 0;
        int rank = 17;
        for (int bit = 30; bit >= 0; bit--) {
            unsigned mid = cur | (1u << bit);
            int c0 = 0;
#pragma unroll
            for (int c = 0; c < 32; c++) {
                unsigned bits = __float_as_uint(v[c]);
                c0 += (bits >= cur && bits < mid) ? 1 : 0;
            }
            c0 = __reduce_add_sync(0xffffffffu, c0);
            if (lane == 0) swarr[wid] = c0;
            __syncthreads();
            int tot = 0;
            for (int w = 0; w < 8; w++) tot += swarr[w];
            if (tot < rank) { rank -= tot; cur = mid; }
            __syncthreads();
        }
        if (tid == 0) s_thr = __uint_as_float(cur);
    }
    __syncthreads();
    const float thr = s_thr;
    const int myl = g_lab[i];

    float ps = 0.0f, ns = 0.0f, fpd = 0.0f;
    int cp = 0, cn = 0, fp = NPTS, anyneg = 0;
#pragma unroll
    for (int c = 0; c < 8; c++) {
        uchar4 l4 = *(const uchar4*)&g_lab[c * 1024 + 4 * tid];
        unsigned char ll[4] = {l4.x, l4.y, l4.z, l4.w};
#pragma unroll
        for (int k = 0; k < 4; k++) {
            int j = c * 1024 + 4 * tid + k;
            if (j == i) continue;
            float dv = v[c * 4 + k];
            bool below = dv < thr;
            if (ll[k] == myl) {
                if (j < fp) { fp = j; fpd = dv; }
                if (below) { ps += __expf(-dv); cp++; }
            } else {
                anyneg = 1;
                if (below) { ns += __expf(-dv); cn++; }
            }
        }
    }
#pragma unroll
    for (int off = 16; off; off >>= 1) {
        ps += __shfl_down_sync(0xffffffffu, ps, off);
        ns += __shfl_down_sync(0xffffffffu, ns, off);
        cp += __shfl_down_sync(0xffffffffu, cp, off);
        cn += __shfl_down_sync(0xffffffffu, cn, off);
        int ofp = __shfl_down_sync(0xffffffffu, fp, off);
        float ofpd = __shfl_down_sync(0xffffffffu, fpd, off);
        if (ofp < fp) { fp = ofp; fpd = ofpd; }
        anyneg |= __shfl_down_sync(0xffffffffu, anyneg, off);
    }
    if (lane == 0) {
        sps[wid] = ps; sns[wid] = ns; scp[wid] = cp; scn[wid] = cn;
        sfp[wid] = fp; sfpd[wid] = fpd; san[wid] = anyneg;
    }
    __syncthreads();
    if (tid == 0) {
        ps = 0; ns = 0; cp = 0; cn = 0; fp = NPTS; fpd = 0; anyneg = 0;
        for (int w = 0; w < 8; w++) {
            ps += sps[w]; ns += sns[w]; cp += scp[w]; cn += scn[w];
            if (sfp[w] < fp) { fp = sfp[w]; fpd = sfpd[w]; }
            anyneg |= san[w];
        }
        bool haspos = (fp < NPTS);
        bool validr = haspos && (anyneg != 0);
        float pos_eff = (cp == 0) ? (haspos ? __expf(-fpd) : 1.0f) : ps;
        float loss_i = validr ? __logf((pos_eff + ns) / pos_eff) : 0.0f;
        int cpa = (cp == 0) ? 1 : cp;
        g_loss[i] = loss_i;
        g_accv[i] = (validr && cpa > cn) ? 1.0f : 0.0f;
        g_tpv[i]  = validr ? (float)cp : 0.0f;
        g_tnv[i]  = validr ? (float)cn : 0.0f;
    }
}

// ---------------- deterministic final reduction ----------------
__global__ void finalize_kernel(float* __restrict__ out) {
    __shared__ float s0[256], s1[256], s2[256], s3[256];
    int tid = threadIdx.x;
    float a = 0, b = 0, c = 0, d = 0;
    for (int j = tid; j < NPTS; j += 256) {
        a += g_loss[j]; b += g_accv[j]; c += g_tpv[j]; d += g_tnv[j];
    }
    s0[tid] = a; s1[tid] = b; s2[tid] = c; s3[tid] = d;
    __syncthreads();
    for (int off = 128; off; off >>= 1) {
        if (tid < off) {
            s0[tid] += s0[tid + off];
            s1[tid] += s1[tid + off];
            s2[tid] += s2[tid + off];
            s3[tid] += s3[tid + off];
        }
        __syncthreads();
    }
    if (tid == 0) {
        const float inv = 1.0f / (float)NPTS;
        out[0] = s0[0] * inv;  // loss
        out[1] = s1[0] * inv;  // accuracy
        out[2] = s2[0] * inv;  // tp
        out[3] = s3[0] * inv;  // tn
    }
}

extern "C" void kernel_launch(void* const* d_in, const int* in_sizes, int n_in,
                              void* d_out, int out_size) {
    const float* X = (const float*)d_in[0];
    const void* T = d_in[1];
    float* out = (float*)d_out;
    (void)in_sizes; (void)n_in; (void)out_size;

    detect_kernel<<<1, 256>>>((const int*)T);
    conv_kernel<<<(NPTS + 255) / 256, 256>>>(T);
    sq_kernel<<<NPTS, 128>>>(X);
    const int ntiles = (NPTS / 128) * (NPTS / 128 + 1) / 2;  // 2080 triangular tiles
    dist_kernel<<<ntiles, 256>>>(X);
    row_kernel<<<NPTS, 256>>>();
    finalize_kernel<<<1, 256>>>(out);
}